// round 16
// baseline (speedup 1.0000x reference)
#include <cuda_runtime.h>
#include <cuda_fp16.h>
#include <cstdint>
#include <math.h>

// Problem constants
#define BB 2
#define SS 2048
#define EE 1024
#define HH 16
#define DD 64
#define MROWS (BB*SS)          // 4096
#define KDIM 1024
#define N_QKV 3072

// ---------------------------------------------------------------------------
// Scratch (allocation-free: device globals) — fp16 hi/lo splits
// ---------------------------------------------------------------------------
__device__ __half g_qhi[BB*HH*SS*DD];
__device__ __half g_qlo[BB*HH*SS*DD];
__device__ __half g_khi[BB*HH*SS*DD];
__device__ __half g_klo[BB*HH*SS*DD];
__device__ __half g_vhi[BB*HH*SS*DD];          // V: hi only (1-pass PV)

__device__ __half g_hhi[MROWS*KDIM];           // hidden hi
__device__ __half g_hlo[MROWS*KDIM];           // hidden lo
__device__ __half g_ahi[MROWS*KDIM];           // attn-out (hi only; 1-pass proj)
__device__ __half g_wqkvThi[N_QKV*KDIM];       // w_attn^T hi
__device__ __half g_wqkvTlo[N_QKV*KDIM];       // w_attn^T lo (Q/K blocks only)
__device__ __half g_wprojThi[EE*KDIM];         // w_proj^T hi

// ---------------------------------------------------------------------------
// PTX helpers
// ---------------------------------------------------------------------------
__device__ __forceinline__ uint32_t smem_u32(const void* p) {
    uint32_t a;
    asm("{ .reg .u64 t; cvta.to.shared.u64 t, %1; cvt.u32.u64 %0, t; }"
        : "=r"(a) : "l"(p));
    return a;
}

__device__ __forceinline__ void ldm_x4(uint32_t& r0, uint32_t& r1,
                                       uint32_t& r2, uint32_t& r3,
                                       uint32_t addr) {
    asm volatile("ldmatrix.sync.aligned.m8n8.x4.shared.b16 {%0,%1,%2,%3}, [%4];"
                 : "=r"(r0), "=r"(r1), "=r"(r2), "=r"(r3) : "r"(addr));
}
__device__ __forceinline__ void ldm_x4_t(uint32_t& r0, uint32_t& r1,
                                         uint32_t& r2, uint32_t& r3,
                                         uint32_t addr) {
    asm volatile("ldmatrix.sync.aligned.m8n8.x4.trans.shared.b16 {%0,%1,%2,%3}, [%4];"
                 : "=r"(r0), "=r"(r1), "=r"(r2), "=r"(r3) : "r"(addr));
}

__device__ __forceinline__ void mma_f16(float* d, const uint32_t* a,
                                        uint32_t b0, uint32_t b1) {
    asm volatile(
        "mma.sync.aligned.m16n8k16.row.col.f32.f16.f16.f32 "
        "{%0,%1,%2,%3}, {%4,%5,%6,%7}, {%8,%9}, {%0,%1,%2,%3};"
        : "+f"(d[0]), "+f"(d[1]), "+f"(d[2]), "+f"(d[3])
        : "r"(a[0]), "r"(a[1]), "r"(a[2]), "r"(a[3]), "r"(b0), "r"(b1));
}

__device__ __forceinline__ void cpa16(uint32_t dst, const void* src) {
    asm volatile("cp.async.cg.shared.global [%0], [%1], 16;"
                 :: "r"(dst), "l"(src));
}
#define CPA_COMMIT() asm volatile("cp.async.commit_group;" ::: "memory")
#define CPA_WAIT(n)  asm volatile("cp.async.wait_group %0;" :: "n"(n) : "memory")

__device__ __forceinline__ uint32_t packf16(float hi, float lo) {
    uint32_t d;
    asm("cvt.rn.f16x2.f32 %0, %1, %2;" : "=r"(d) : "f"(hi), "f"(lo));
    return d;
}
__device__ __forceinline__ float lof16(uint32_t u) {
    return __half2float(__ushort_as_half((unsigned short)(u & 0xffffu)));
}
__device__ __forceinline__ float hif16(uint32_t u) {
    return __half2float(__ushort_as_half((unsigned short)(u >> 16)));
}
// guaranteed-MUFU exp2 (fp32)
__device__ __forceinline__ float ex2(float x) {
    float y;
    asm("ex2.approx.f32 %0, %1;" : "=f"(y) : "f"(x));
    return y;
}
// paired fp16 exp2 — one MUFU op for two elements
__device__ __forceinline__ uint32_t ex2h2(uint32_t x) {
    uint32_t y;
    asm("ex2.approx.f16x2 %0, %1;" : "=r"(y) : "r"(x));
    return y;
}

// ---------------------------------------------------------------------------
// Fused prep kernel (one launch)
// ---------------------------------------------------------------------------
#define PREP_SPLIT_BLKS 4096
#define PREP_WA_BLKS    3072
#define PREP_TOTAL_BLKS 8192

__global__ __launch_bounds__(256) void prep_kernel(
    const float* __restrict__ x,
    const float* __restrict__ Wa,
    const float* __restrict__ Wp)
{
    __shared__ float t[32][33];
    int bid = blockIdx.x;
    if (bid < PREP_SPLIT_BLKS) {
        size_t i0 = ((size_t)bid * 256 + threadIdx.x) * 4;
        float4 v = *(const float4*)&x[i0];
        __half h0 = __float2half_rn(v.x);
        __half h1 = __float2half_rn(v.y);
        __half h2 = __float2half_rn(v.z);
        __half h3 = __float2half_rn(v.w);
        __half2 hp0; hp0.x = h0; hp0.y = h1;
        __half2 hp1; hp1.x = h2; hp1.y = h3;
        __half2 lp0;
        lp0.x = __float2half_rn(v.x - __half2float(h0));
        lp0.y = __float2half_rn(v.y - __half2float(h1));
        __half2 lp1;
        lp1.x = __float2half_rn(v.z - __half2float(h2));
        lp1.y = __float2half_rn(v.w - __half2float(h3));
        *(__half2*)&g_hhi[i0]     = hp0;
        *(__half2*)&g_hhi[i0 + 2] = hp1;
        *(__half2*)&g_hlo[i0]     = lp0;
        *(__half2*)&g_hlo[i0 + 2] = lp1;
        return;
    }
    int which, N, n0, k0;
    if (bid < PREP_SPLIT_BLKS + PREP_WA_BLKS) {
        int tt = bid - PREP_SPLIT_BLKS;
        which = 0; N = N_QKV;
        n0 = (tt % 96) * 32; k0 = (tt / 96) * 32;
    } else {
        int tt = bid - PREP_SPLIT_BLKS - PREP_WA_BLKS;
        which = 1; N = EE;
        n0 = (tt % 32) * 32; k0 = (tt / 32) * 32;
    }
    const float* W = which ? Wp : Wa;
    int tx = threadIdx.x & 31, ty = threadIdx.x >> 5;
#pragma unroll
    for (int r = 0; r < 32; r += 8)
        t[ty + r][tx] = W[(size_t)(k0 + ty + r) * N + n0 + tx];
    __syncthreads();
#pragma unroll
    for (int r = 0; r < 32; r += 8) {
        float v = t[tx][ty + r];
        __half h = __float2half_rn(v);
        size_t o = (size_t)(n0 + ty + r) * KDIM + k0 + tx;
        if (which) {
            g_wprojThi[o] = h;
        } else {
            g_wqkvThi[o] = h;
            g_wqkvTlo[o] = __float2half_rn(v - __half2float(h));
        }
    }
}

// ---------------------------------------------------------------------------
// Tensor-core GEMM: fp16 split, 3-stage cp.async, XOR-swizzled smem.
// p3 tiles (QKV Q/K): BK=32, 3-pass, 32 iterations.
// 1-pass tiles (QKV V; proj): BK=64 (two 32-col sub-arrays/stage), 16 iters.
// ---------------------------------------------------------------------------
#define BK 32
#define GARR 8192u
#define GSTAGE (4u * GARR)
#define GEMM_SMEM_BYTES (3 * GSTAGE)

__global__ __launch_bounds__(256, 2) void mma_gemm(const float* __restrict__ bias,
                                                   float* __restrict__ outp,
                                                   int mode)
{
    extern __shared__ __half gsm[];
    uint32_t sbase = smem_u32(gsm);
    uint32_t send = sbase + 3u * GSTAGE;

    const __half* Ahi = mode ? g_hhi : g_ahi;
    const __half* Alo = g_hlo;
    const __half* Bhi = mode ? g_wqkvThi : g_wprojThi;
    const __half* Blo = g_wqkvTlo;

    int tid = threadIdx.x;
    int wid = tid >> 5, lane = tid & 31;
    int warp_m = wid & 1, warp_n = wid >> 1;

    int bid = blockIdx.x;
    int bx, by;
    if (mode) {
        if (bid < 512) { by = bid >> 4; bx = bid & 15; }
        else { int tt = bid - 512; by = tt >> 3; bx = 16 + (tt & 7); }
    } else {
        bx = bid & 7; by = bid >> 3;
    }
    int m0 = by * 128, n0 = bx * 128;
    const int p3 = (mode == 1) && (n0 < 2048);

    float acc[4][4][4];
#pragma unroll
    for (int i = 0; i < 4; i++)
#pragma unroll
        for (int j = 0; j < 4; j++)
#pragma unroll
            for (int r = 0; r < 4; r++) acc[i][j][r] = 0.0f;

    int lr = tid >> 1;
    int lv0 = (tid & 1) * 2;
    uint32_t swr = (uint32_t)((lr >> 1) & 3);
    uint32_t soff[2];
#pragma unroll
    for (int vv = 0; vv < 2; vv++) {
        uint32_t v = (uint32_t)(lv0 + vv);
        soff[vv] = (uint32_t)(lr * 64) + ((v ^ swr) << 4);
    }

    // p3 stage loads: BK=32, arrays {Ahi, Alo, Bhi, Blo}
    auto load_stage_p3 = [&](uint32_t sb, int kc) {
#pragma unroll
        for (int vv = 0; vv < 2; vv++) {
            int v = lv0 + vv;
            size_t asrc = (size_t)(m0 + lr) * KDIM + kc + v * 8;
            size_t bsrc = (size_t)(n0 + lr) * KDIM + kc + v * 8;
            uint32_t o = soff[vv];
            cpa16(sb + o,             Ahi + asrc);
            cpa16(sb + GARR + o,      Alo + asrc);
            cpa16(sb + 2 * GARR + o,  Bhi + bsrc);
            cpa16(sb + 3 * GARR + o,  Blo + bsrc);
        }
    };
    // 1-pass stage loads: BK=64, arrays {A c0, A c1, B c0, B c1}
    auto load_stage_1p = [&](uint32_t sb, int kc) {
#pragma unroll
        for (int vv = 0; vv < 2; vv++) {
            int v = lv0 + vv;
            size_t asrc = (size_t)(m0 + lr) * KDIM + kc + v * 8;
            size_t bsrc = (size_t)(n0 + lr) * KDIM + kc + v * 8;
            uint32_t o = soff[vv];
            cpa16(sb + o,             Ahi + asrc);
            cpa16(sb + GARR + o,      Ahi + asrc + 32);
            cpa16(sb + 2 * GARR + o,  Bhi + bsrc);
            cpa16(sb + 3 * GARR + o,  Bhi + bsrc + 32);
        }
    };

    int lrow = lane & 15, lcol = lane >> 4;
    uint32_t x = (uint32_t)((lrow >> 1) & 3);
    uint32_t coff0 = (((uint32_t)lcol ^ x) << 4);
    uint32_t coff1 = ((((uint32_t)lcol + 2u) ^ x) << 4);
    uint32_t aoff[4], boff[2];
#pragma unroll
    for (int mf = 0; mf < 4; mf++)
        aoff[mf] = (uint32_t)((warp_m * 64 + mf * 16 + lrow) * 64);
#pragma unroll
    for (int pf = 0; pf < 2; pf++)
        boff[pf] = (uint32_t)((warp_n * 32 + pf * 16 + lrow) * 64);

    if (p3) {
        // ---------------- BK=32, 3-pass path ----------------
        load_stage_p3(sbase, 0);
        CPA_COMMIT();
        load_stage_p3(sbase + GSTAGE, BK);
        CPA_COMMIT();

        uint32_t sb_c = sbase;
        uint32_t sb_l = sbase + 2u * GSTAGE;

        const int NITER = KDIM / BK;      // 32
        for (int c = 0; c < NITER; c++) {
            if (c < NITER - 1) { CPA_WAIT(1); } else { CPA_WAIT(0); }
            __syncthreads();
            if (c + 2 < NITER) {
                load_stage_p3(sb_l, (c + 2) * BK);
                CPA_COMMIT();
                sb_l += GSTAGE; if (sb_l == send) sb_l = sbase;
            }
            uint32_t sb = sb_c;
            sb_c += GSTAGE; if (sb_c == send) sb_c = sbase;

#pragma unroll
            for (int ki = 0; ki < 2; ki++) {
                uint32_t coff = ki ? coff1 : coff0;
                uint32_t ah[4][4];
#pragma unroll
                for (int mf = 0; mf < 4; mf++)
                    ldm_x4(ah[mf][0], ah[mf][1], ah[mf][2], ah[mf][3],
                           sb + aoff[mf] + coff);
                uint32_t bh[4][2];
#pragma unroll
                for (int pf = 0; pf < 2; pf++) {
                    uint32_t r0, r1, r2, r3;
                    ldm_x4(r0, r1, r2, r3, sb + 2 * GARR + boff[pf] + coff);
                    bh[pf * 2 + 0][0] = r0; bh[pf * 2 + 0][1] = r2;
                    bh[pf * 2 + 1][0] = r1; bh[pf * 2 + 1][1] = r3;
                }
#pragma unroll
                for (int mf = 0; mf < 4; mf++)
#pragma unroll
                    for (int nf = 0; nf < 4; nf++)
                        mma_f16(acc[mf][nf], ah[mf], bh[nf][0], bh[nf][1]);
                uint32_t al[4][4];
#pragma unroll
                for (int mf = 0; mf < 4; mf++)
                    ldm_x4(al[mf][0], al[mf][1], al[mf][2], al[mf][3],
                           sb + GARR + aoff[mf] + coff);
#pragma unroll
                for (int mf = 0; mf < 4; mf++)
#pragma unroll
                    for (int nf = 0; nf < 4; nf++)
                        mma_f16(acc[mf][nf], al[mf], bh[nf][0], bh[nf][1]);
                uint32_t bl[4][2];
#pragma unroll
                for (int pf = 0; pf < 2; pf++) {
                    uint32_t r0, r1, r2, r3;
                    ldm_x4(r0, r1, r2, r3, sb + 3 * GARR + boff[pf] + coff);
                    bl[pf * 2 + 0][0] = r0; bl[pf * 2 + 0][1] = r2;
                    bl[pf * 2 + 1][0] = r1; bl[pf * 2 + 1][1] = r3;
                }
#pragma unroll
                for (int mf = 0; mf < 4; mf++)
#pragma unroll
                    for (int nf = 0; nf < 4; nf++)
                        mma_f16(acc[mf][nf], ah[mf], bl[nf][0], bl[nf][1]);
            }
        }
    } else {
        // ---------------- BK=64, 1-pass path ----------------
        load_stage_1p(sbase, 0);
        CPA_COMMIT();
        load_stage_1p(sbase + GSTAGE, 64);
        CPA_COMMIT();

        uint32_t sb_c = sbase;
        uint32_t sb_l = sbase + 2u * GSTAGE;

        const int NITER = KDIM / 64;      // 16
        for (int c = 0; c < NITER; c++) {
            if (c < NITER - 1) { CPA_WAIT(1); } else { CPA_WAIT(0); }
            __syncthreads();
            if (c + 2 < NITER) {
                load_stage_1p(sb_l, (c + 2) * 64);
                CPA_COMMIT();
                sb_l += GSTAGE; if (sb_l == send) sb_l = sbase;
            }
            uint32_t sb = sb_c;
            sb_c += GSTAGE; if (sb_c == send) sb_c = sbase;

#pragma unroll
            for (int sub = 0; sub < 2; sub++) {
                uint32_t asb = sb + (uint32_t)sub * GARR;
                uint32_t bsb = sb + (uint32_t)(2 + sub) * GARR;
#pragma unroll
                for (int ki = 0; ki < 2; ki++) {
                    uint32_t coff = ki ? coff1 : coff0;
                    uint32_t ah[4][4];
#pragma unroll
                    for (int mf = 0; mf < 4; mf++)
                        ldm_x4(ah[mf][0], ah[mf][1], ah[mf][2], ah[mf][3],
                               asb + aoff[mf] + coff);
                    uint32_t bh[4][2];
#pragma unroll
                    for (int pf = 0; pf < 2; pf++) {
                        uint32_t r0, r1, r2, r3;
                        ldm_x4(r0, r1, r2, r3, bsb + boff[pf] + coff);
                        bh[pf * 2 + 0][0] = r0; bh[pf * 2 + 0][1] = r2;
                        bh[pf * 2 + 1][0] = r1; bh[pf * 2 + 1][1] = r3;
                    }
#pragma unroll
                    for (int mf = 0; mf < 4; mf++)
#pragma unroll
                        for (int nf = 0; nf < 4; nf++)
                            mma_f16(acc[mf][nf], ah[mf], bh[nf][0], bh[nf][1]);
                }
            }
        }
    }

    // Epilogue
    int gID = lane >> 2, tcol = lane & 3;
#pragma unroll
    for (int mf = 0; mf < 4; mf++) {
#pragma unroll
        for (int nf = 0; nf < 4; nf++) {
            int c = n0 + warp_n * 32 + nf * 8 + tcol * 2;
            float2 bv = *(const float2*)&bias[c];
#pragma unroll
            for (int half = 0; half < 2; half++) {
                int r = m0 + warp_m * 64 + mf * 16 + gID + half * 8;
                float2 v;
                v.x = acc[mf][nf][half * 2 + 0] + bv.x;
                v.y = acc[mf][nf][half * 2 + 1] + bv.y;
                if (mode == 0) {
                    *(float2*)&outp[(size_t)r * EE + c] = v;
                } else {
                    int part = c >> 10, e = c & 1023, h = e >> 6, d0 = e & 63;
                    int b = r >> 11, s = r & 2047;
                    size_t base = (((size_t)(b * HH + h)) * SS + s) * DD + d0;
                    uint32_t hp = packf16(v.y, v.x);
                    if (part == 2) {
                        *(uint32_t*)&g_vhi[base] = hp;
                    } else {
                        uint32_t lp = packf16(v.y - hif16(hp), v.x - lof16(hp));
                        if (part == 0) {
                            *(uint32_t*)&g_qhi[base] = hp;
                            *(uint32_t*)&g_qlo[base] = lp;
                        } else {
                            *(uint32_t*)&g_khi[base] = hp;
                            *(uint32_t*)&g_klo[base] = lp;
                        }
                    }
                }
            }
        }
    }
}

// ---------------------------------------------------------------------------
// Tensor-core causal flash attention: QK^T 3-pass fp16 split, PV 1-pass,
// Q frags in registers, 3-stage KV ring (stage2 overlays ONLY the Q region),
// f16x2 paired MUFU softmax.
// Layout: [0, AQ) = Q (stage2 overlays it post-hoist),
//         [AQ, AQ+stg) = stage0, [AQ+stg, AQ+2stg) = stage1.
// ---------------------------------------------------------------------------
#define ALD 72
#define AQ_BYTES (2 * 128 * ALD * 2)          // 36864 (Qhi + Qlo)
#define AKV_ARR (64 * ALD)                    // elems per K/V array
#define AKV_STG_BYTES (3 * AKV_ARR * 2)       // 27648 (Khi,Klo,Vhi)
#define ATTN_SMEM_BYTES (AQ_BYTES + 2 * AKV_STG_BYTES)   // 92160

#define LOG2E 1.4426950408889634f

__global__ __launch_bounds__(256, 2) void attn_mma_kernel()
{
    extern __shared__ __half dsm[];
    __half* Qhi_s = dsm;
    __half* Qlo_s = dsm + 128 * ALD;
    uint32_t sbase = smem_u32(dsm);
    uint32_t stageb0 = sbase + (uint32_t)AQ_BYTES;                    // after Q
    uint32_t stageb1 = sbase + (uint32_t)(AQ_BYTES + AKV_STG_BYTES);  // after s0
    uint32_t stageb2 = sbase;                 // overlays Q (safe post-hoist)

    int qt = gridDim.x - 1 - blockIdx.x;        // big tiles first
    int h  = blockIdx.y;
    int b  = blockIdx.z;
    int tid = threadIdx.x, wid = tid >> 5, lane = tid & 31;

    size_t bh = ((size_t)(b * HH + h)) * SS * DD;
    const __half* Qhg = g_qhi + bh;
    const __half* Qlg = g_qlo + bh;
    const __half* Khg = g_khi + bh;
    const __half* Klg = g_klo + bh;
    const __half* Vhg = g_vhi + bh;

    int q0 = qt * 128;
    int ktmax = 2 * qt + 1;                     // >= 1 always

    auto load_kv = [&](uint32_t sb, int k0) {
#pragma unroll
        for (int t = 0; t < 2; t++) {
            int i = tid + t * 256;
            int r = i >> 3, v = i & 7;
            size_t src = (size_t)(k0 + r) * DD + v * 8;
            uint32_t o = (uint32_t)((r * ALD + v * 8) * 2);
            cpa16(sb + o,                   Khg + src);
            cpa16(sb + AKV_ARR * 2 + o,     Klg + src);
            cpa16(sb + 2 * AKV_ARR * 2 + o, Vhg + src);
        }
    };

    // Stages 0 and 1 live outside the Q region: issue both immediately.
    load_kv(stageb0, 0);
    CPA_COMMIT();
    load_kv(stageb1, 64);     // kt=1 data; valid since ktmax >= 1
    CPA_COMMIT();

    // Q tile into smem (plain stores)
#pragma unroll
    for (int t = 0; t < 4; t++) {
        int i = tid + t * 256;
        int r = i >> 3, v = i & 7;
        size_t src = (size_t)(q0 + r) * DD + v * 8;
        uint32_t so = (uint32_t)(r * ALD + v * 8);
        *(uint4*)&Qhi_s[so] = *(const uint4*)(Qhg + src);
        *(uint4*)&Qlo_s[so] = *(const uint4*)(Qlg + src);
    }

    int lrow = lane & 15, lcol = lane >> 4;
    uint32_t qb_hi = sbase +
        (uint32_t)(((wid * 16 + lrow) * ALD + lcol * 8) * 2);
    uint32_t qb_lo = qb_hi + (uint32_t)(128 * ALD * 2);
    uint32_t kvo = (uint32_t)((lrow * ALD + lcol * 8) * 2);

    __syncthreads();                 // Q smem visible to all warps
    uint32_t qh[4][4], ql[4][4];
#pragma unroll
    for (int ks = 0; ks < 4; ks++) {
        ldm_x4(qh[ks][0], qh[ks][1], qh[ks][2], qh[ks][3],
               qb_hi + (uint32_t)(ks * 32));
        ldm_x4(ql[ks][0], ql[ks][1], ql[ks][2], ql[ks][3],
               qb_lo + (uint32_t)(ks * 32));
    }
    __syncthreads();                 // all hoists done before any overlay write

    float o[8][4];
#pragma unroll
    for (int j = 0; j < 8; j++)
#pragma unroll
        for (int e = 0; e < 4; e++) o[j][e] = 0.0f;
    float m_[2] = {-1e30f, -1e30f}, l_[2] = {0.0f, 0.0f};

    int row0 = q0 + wid * 16 + (lane >> 2);
    const float scale2 = (1.0f / 16.0f) * LOG2E;
    const float maskv = -10000.0f * LOG2E;

    int s_c = 0;                     // compute stage idx
    int s_l = 2;                     // next load stage idx (stage2 = overlay)

    for (int kt = 0; kt <= ktmax; kt++) {
        if (kt < ktmax) { CPA_WAIT(1); } else { CPA_WAIT(0); }
        __syncthreads();
        if (kt + 2 <= ktmax) {
            uint32_t lb = (s_l == 0) ? stageb0 : (s_l == 1) ? stageb1 : stageb2;
            load_kv(lb, (kt + 2) * 64);
            CPA_COMMIT();
            s_l = (s_l == 2) ? 0 : s_l + 1;
        }
        uint32_t sb = (s_c == 0) ? stageb0 : (s_c == 1) ? stageb1 : stageb2;
        s_c = (s_c == 2) ? 0 : s_c + 1;

        uint32_t kb_hi = sb + kvo;
        uint32_t kb_lo = sb + AKV_ARR * 2 + kvo;
        uint32_t vb_hi = sb + 2 * AKV_ARR * 2 + kvo;
        int k0 = kt * 64;

        float s[8][4];
#pragma unroll
        for (int nf = 0; nf < 8; nf++)
#pragma unroll
            for (int e = 0; e < 4; e++) s[nf][e] = 0.0f;

#pragma unroll
        for (int ks = 0; ks < 4; ks++) {
#pragma unroll
            for (int g = 0; g < 4; g++) {
                uint32_t off = (uint32_t)((g * 16 * ALD + ks * 16) * 2);
                uint32_t r0, r1, r2, r3, t0, t1, t2, t3;
                ldm_x4(r0, r1, r2, r3, kb_hi + off);
                ldm_x4(t0, t1, t2, t3, kb_lo + off);
                mma_f16(s[2 * g],     qh[ks], r0, r2);
                mma_f16(s[2 * g + 1], qh[ks], r1, r3);
                mma_f16(s[2 * g],     ql[ks], r0, r2);
                mma_f16(s[2 * g + 1], ql[ks], r1, r3);
                mma_f16(s[2 * g],     qh[ks], t0, t2);
                mma_f16(s[2 * g + 1], qh[ks], t1, t3);
            }
        }

        if (kt >= ktmax - 1) {
#pragma unroll
            for (int nf = 0; nf < 8; nf++) {
                int cb = k0 + nf * 8 + (lane & 3) * 2;
#pragma unroll
                for (int e = 0; e < 4; e++) {
                    int col = cb + (e & 1);
                    int row = (e < 2) ? row0 : row0 + 8;
                    float v = s[nf][e] * scale2;
                    s[nf][e] = (col > row) ? maskv : v;
                }
            }
        } else {
#pragma unroll
            for (int nf = 0; nf < 8; nf++)
#pragma unroll
                for (int e = 0; e < 4; e++) s[nf][e] *= scale2;
        }

        // online softmax (log2 domain): paired f16x2 exp; p = PV A-fragments
        uint32_t ps[2][8];
#pragma unroll
        for (int i = 0; i < 2; i++) {
            float mx = -1e30f;
#pragma unroll
            for (int nf = 0; nf < 8; nf++)
                mx = fmaxf(mx, fmaxf(s[nf][2 * i], s[nf][2 * i + 1]));
            mx = fmaxf(mx, __shfl_xor_sync(0xffffffffu, mx, 1));
            mx = fmaxf(mx, __shfl_xor_sync(0xffffffffu, mx, 2));
            float mn = fmaxf(m_[i], mx);
            float alpha = ex2(m_[i] - mn);
#pragma unroll
            for (int nf = 0; nf < 8; nf++)
                ps[i][nf] = ex2h2(packf16(s[nf][2 * i + 1] - mn,
                                          s[nf][2 * i] - mn));
            float sum = 0.0f;
#pragma unroll
            for (int nf = 0; nf < 8; nf++)
                sum += lof16(ps[i][nf]) + hif16(ps[i][nf]);
            sum += __shfl_xor_sync(0xffffffffu, sum, 1);
            sum += __shfl_xor_sync(0xffffffffu, sum, 2);
            l_[i] = l_[i] * alpha + sum;
            m_[i] = mn;
#pragma unroll
            for (int j = 0; j < 8; j++) {
                o[j][2 * i] *= alpha; o[j][2 * i + 1] *= alpha;
            }
        }

        // O += P V  (1-pass)
#pragma unroll
        for (int c = 0; c < 4; c++) {
            uint32_t aph[4];
            aph[0] = ps[0][2 * c];
            aph[1] = ps[1][2 * c];
            aph[2] = ps[0][2 * c + 1];
            aph[3] = ps[1][2 * c + 1];
#pragma unroll
            for (int g = 0; g < 4; g++) {
                uint32_t off = (uint32_t)((c * 16 * ALD + g * 16) * 2);
                uint32_t r0, r1, r2, r3;
                ldm_x4_t(r0, r1, r2, r3, vb_hi + off);
                mma_f16(o[2 * g],     aph, r0, r1);
                mma_f16(o[2 * g + 1], aph, r2, r3);
            }
        }
    }

    // epilogue: O/l -> fp16 (hi only) merged-head [B*S, E]
    float inv0 = 1.0f / l_[0], inv1 = 1.0f / l_[1];
    int d0 = (lane & 3) * 2;
    size_t rb0 = ((size_t)(b * SS + row0)) * EE + h * DD;
    size_t rb1 = rb0 + (size_t)8 * EE;
#pragma unroll
    for (int j = 0; j < 8; j++) {
        int d = j * 8 + d0;
        float v0 = o[j][0] * inv0, v1 = o[j][1] * inv0;
        float v2 = o[j][2] * inv1, v3 = o[j][3] * inv1;
        *(uint32_t*)&g_ahi[rb0 + d] = packf16(v1, v0);
        *(uint32_t*)&g_ahi[rb1 + d] = packf16(v3, v2);
    }
}

// ---------------------------------------------------------------------------
extern "C" void kernel_launch(void* const* d_in, const int* in_sizes, int n_in,
                              void* d_out, int out_size)
{
    const float* hidden = (const float*)d_in[0];   // [B,S,E]
    const float* w_attn = (const float*)d_in[1];   // [E, 3E]
    const float* b_attn = (const float*)d_in[2];   // [3E]
    const float* w_proj = (const float*)d_in[3];   // [E, E]
    const float* b_proj = (const float*)d_in[4];   // [E]
    float* out = (float*)d_out;                    // [B,S,E] fp32

    prep_kernel<<<PREP_TOTAL_BLKS, 256>>>(hidden, w_attn, w_proj);

    cudaFuncSetAttribute(mma_gemm, cudaFuncAttributeMaxDynamicSharedMemorySize,
                         GEMM_SMEM_BYTES);
    mma_gemm<<<768, 256, GEMM_SMEM_BYTES>>>(b_attn, nullptr, 1);

    cudaFuncSetAttribute(attn_mma_kernel,
                         cudaFuncAttributeMaxDynamicSharedMemorySize,
                         ATTN_SMEM_BYTES);
    attn_mma_kernel<<<dim3(SS / 128, HH, BB), 256, ATTN_SMEM_BYTES>>>();

    mma_gemm<<<256, 256, GEMM_SMEM_BYTES>>>(b_proj, out, 0);
}

// round 17
// speedup vs baseline: 1.0170x; 1.0170x over previous
#include <cuda_runtime.h>
#include <cuda_fp16.h>
#include <cstdint>
#include <math.h>

// Problem constants
#define BB 2
#define SS 2048
#define EE 1024
#define HH 16
#define DD 64
#define MROWS (BB*SS)          // 4096
#define KDIM 1024
#define N_QKV 3072

// ---------------------------------------------------------------------------
// Scratch (allocation-free: device globals) — fp16 hi/lo splits
// ---------------------------------------------------------------------------
__device__ __half g_qhi[BB*HH*SS*DD];
__device__ __half g_qlo[BB*HH*SS*DD];
__device__ __half g_khi[BB*HH*SS*DD];
__device__ __half g_klo[BB*HH*SS*DD];
__device__ __half g_vhi[BB*HH*SS*DD];          // V: hi only (1-pass PV)

__device__ __half g_hhi[MROWS*KDIM];           // hidden hi
__device__ __half g_hlo[MROWS*KDIM];           // hidden lo
__device__ __half g_ahi[MROWS*KDIM];           // attn-out (hi only; 1-pass proj)
__device__ __half g_wqkvThi[N_QKV*KDIM];       // w_attn^T hi
__device__ __half g_wqkvTlo[N_QKV*KDIM];       // w_attn^T lo (Q/K blocks only)
__device__ __half g_wprojThi[EE*KDIM];         // w_proj^T hi

// ---------------------------------------------------------------------------
// PTX helpers
// ---------------------------------------------------------------------------
__device__ __forceinline__ uint32_t smem_u32(const void* p) {
    uint32_t a;
    asm("{ .reg .u64 t; cvta.to.shared.u64 t, %1; cvt.u32.u64 %0, t; }"
        : "=r"(a) : "l"(p));
    return a;
}

__device__ __forceinline__ void ldm_x4(uint32_t& r0, uint32_t& r1,
                                       uint32_t& r2, uint32_t& r3,
                                       uint32_t addr) {
    asm volatile("ldmatrix.sync.aligned.m8n8.x4.shared.b16 {%0,%1,%2,%3}, [%4];"
                 : "=r"(r0), "=r"(r1), "=r"(r2), "=r"(r3) : "r"(addr));
}
__device__ __forceinline__ void ldm_x4_t(uint32_t& r0, uint32_t& r1,
                                         uint32_t& r2, uint32_t& r3,
                                         uint32_t addr) {
    asm volatile("ldmatrix.sync.aligned.m8n8.x4.trans.shared.b16 {%0,%1,%2,%3}, [%4];"
                 : "=r"(r0), "=r"(r1), "=r"(r2), "=r"(r3) : "r"(addr));
}

__device__ __forceinline__ void mma_f16(float* d, const uint32_t* a,
                                        uint32_t b0, uint32_t b1) {
    asm volatile(
        "mma.sync.aligned.m16n8k16.row.col.f32.f16.f16.f32 "
        "{%0,%1,%2,%3}, {%4,%5,%6,%7}, {%8,%9}, {%0,%1,%2,%3};"
        : "+f"(d[0]), "+f"(d[1]), "+f"(d[2]), "+f"(d[3])
        : "r"(a[0]), "r"(a[1]), "r"(a[2]), "r"(a[3]), "r"(b0), "r"(b1));
}

__device__ __forceinline__ void cpa16(uint32_t dst, const void* src) {
    asm volatile("cp.async.cg.shared.global [%0], [%1], 16;"
                 :: "r"(dst), "l"(src));
}
#define CPA_COMMIT() asm volatile("cp.async.commit_group;" ::: "memory")
#define CPA_WAIT(n)  asm volatile("cp.async.wait_group %0;" :: "n"(n) : "memory")

__device__ __forceinline__ uint32_t packf16(float hi, float lo) {
    uint32_t d;
    asm("cvt.rn.f16x2.f32 %0, %1, %2;" : "=r"(d) : "f"(hi), "f"(lo));
    return d;
}
__device__ __forceinline__ float lof16(uint32_t u) {
    return __half2float(__ushort_as_half((unsigned short)(u & 0xffffu)));
}
__device__ __forceinline__ float hif16(uint32_t u) {
    return __half2float(__ushort_as_half((unsigned short)(u >> 16)));
}
// guaranteed-MUFU exp2 (fp32)
__device__ __forceinline__ float ex2(float x) {
    float y;
    asm("ex2.approx.f32 %0, %1;" : "=f"(y) : "f"(x));
    return y;
}
// paired fp16 exp2 — one MUFU op for two elements
__device__ __forceinline__ uint32_t ex2h2(uint32_t x) {
    uint32_t y;
    asm("ex2.approx.f16x2 %0, %1;" : "=r"(y) : "r"(x));
    return y;
}

// ---------------------------------------------------------------------------
// Fused prep kernel (one launch):
//   bid [0, 4096):            split hidden fp32 -> fp16 hi/lo
//   bid [4096, 4096+1536):    w_attn^T hi/lo, 64(k)x32(n) tiles, 128B stores
//   bid [.., +512):           w_proj^T hi,    64(k)x32(n) tiles
// ---------------------------------------------------------------------------
#define PREP_SPLIT_BLKS 4096
#define PREP_WA_BLKS    (96 * 16)   // (3072/32) n-tiles x (1024/64) k-tiles
#define PREP_WP_BLKS    (32 * 16)
#define PREP_TOTAL_BLKS (PREP_SPLIT_BLKS + PREP_WA_BLKS + PREP_WP_BLKS)

__global__ __launch_bounds__(256) void prep_kernel(
    const float* __restrict__ x,
    const float* __restrict__ Wa,
    const float* __restrict__ Wp)
{
    __shared__ float t[64][33];
    int bid = blockIdx.x;
    int tid = threadIdx.x;
    if (bid < PREP_SPLIT_BLKS) {
        size_t i0 = ((size_t)bid * 256 + tid) * 4;
        float4 v = *(const float4*)&x[i0];
        __half h0 = __float2half_rn(v.x);
        __half h1 = __float2half_rn(v.y);
        __half h2 = __float2half_rn(v.z);
        __half h3 = __float2half_rn(v.w);
        __half2 hp0; hp0.x = h0; hp0.y = h1;
        __half2 hp1; hp1.x = h2; hp1.y = h3;
        __half2 lp0;
        lp0.x = __float2half_rn(v.x - __half2float(h0));
        lp0.y = __float2half_rn(v.y - __half2float(h1));
        __half2 lp1;
        lp1.x = __float2half_rn(v.z - __half2float(h2));
        lp1.y = __float2half_rn(v.w - __half2float(h3));
        *(__half2*)&g_hhi[i0]     = hp0;
        *(__half2*)&g_hhi[i0 + 2] = hp1;
        *(__half2*)&g_hlo[i0]     = lp0;
        *(__half2*)&g_hlo[i0 + 2] = lp1;
        return;
    }
    // transpose-split branch: 64(k) x 32(n) tiles
    int which, N, n0, k0;
    if (bid < PREP_SPLIT_BLKS + PREP_WA_BLKS) {
        int tt = bid - PREP_SPLIT_BLKS;
        which = 0; N = N_QKV;
        n0 = (tt % 96) * 32; k0 = (tt / 96) * 64;
    } else {
        int tt = bid - PREP_SPLIT_BLKS - PREP_WA_BLKS;
        which = 1; N = EE;
        n0 = (tt % 32) * 32; k0 = (tt / 32) * 64;
    }
    const float* W = which ? Wp : Wa;
    int tx = tid & 31, ty = tid >> 5;          // ty 0..7
#pragma unroll
    for (int r = 0; r < 64; r += 8)
        t[ty + r][tx] = W[(size_t)(k0 + ty + r) * N + n0 + tx];
    __syncthreads();
    // each thread: one output row n, 8 contiguous k -> 16B vector stores
    int n = tid >> 3;                   // 0..31
    int kk = (tid & 7) * 8;             // 0..56
    __half hbuf[8], lbuf[8];
#pragma unroll
    for (int j = 0; j < 8; j++) {
        float v = t[kk + j][n];
        __half hh = __float2half_rn(v);
        hbuf[j] = hh;
        lbuf[j] = __float2half_rn(v - __half2float(hh));
    }
    size_t o = (size_t)(n0 + n) * KDIM + k0 + kk;
    if (which) {
        *(uint4*)&g_wprojThi[o] = *(uint4*)hbuf;
    } else {
        *(uint4*)&g_wqkvThi[o] = *(uint4*)hbuf;
        *(uint4*)&g_wqkvTlo[o] = *(uint4*)lbuf;
    }
}

// ---------------------------------------------------------------------------
// Tensor-core GEMM: fp16 split, 3-stage cp.async, XOR-swizzled smem.
// p3 tiles (QKV Q/K): BK=32, 3-pass, 32 iterations.
// 1-pass tiles (QKV V; proj): BK=64 (two 32-col sub-arrays/stage), 16 iters.
// ---------------------------------------------------------------------------
#define BK 32
#define GARR 8192u
#define GSTAGE (4u * GARR)
#define GEMM_SMEM_BYTES (3 * GSTAGE)

__global__ __launch_bounds__(256, 2) void mma_gemm(const float* __restrict__ bias,
                                                   float* __restrict__ outp,
                                                   int mode)
{
    extern __shared__ __half gsm[];
    uint32_t sbase = smem_u32(gsm);
    uint32_t send = sbase + 3u * GSTAGE;

    const __half* Ahi = mode ? g_hhi : g_ahi;
    const __half* Alo = g_hlo;
    const __half* Bhi = mode ? g_wqkvThi : g_wprojThi;
    const __half* Blo = g_wqkvTlo;

    int tid = threadIdx.x;
    int wid = tid >> 5, lane = tid & 31;
    int warp_m = wid & 1, warp_n = wid >> 1;

    int bid = blockIdx.x;
    int bx, by;
    if (mode) {
        if (bid < 512) { by = bid >> 4; bx = bid & 15; }
        else { int tt = bid - 512; by = tt >> 3; bx = 16 + (tt & 7); }
    } else {
        bx = bid & 7; by = bid >> 3;
    }
    int m0 = by * 128, n0 = bx * 128;
    const int p3 = (mode == 1) && (n0 < 2048);

    float acc[4][4][4];
#pragma unroll
    for (int i = 0; i < 4; i++)
#pragma unroll
        for (int j = 0; j < 4; j++)
#pragma unroll
            for (int r = 0; r < 4; r++) acc[i][j][r] = 0.0f;

    int lr = tid >> 1;
    int lv0 = (tid & 1) * 2;
    uint32_t swr = (uint32_t)((lr >> 1) & 3);
    uint32_t soff[2];
#pragma unroll
    for (int vv = 0; vv < 2; vv++) {
        uint32_t v = (uint32_t)(lv0 + vv);
        soff[vv] = (uint32_t)(lr * 64) + ((v ^ swr) << 4);
    }

    auto load_stage_p3 = [&](uint32_t sb, int kc) {
#pragma unroll
        for (int vv = 0; vv < 2; vv++) {
            int v = lv0 + vv;
            size_t asrc = (size_t)(m0 + lr) * KDIM + kc + v * 8;
            size_t bsrc = (size_t)(n0 + lr) * KDIM + kc + v * 8;
            uint32_t o = soff[vv];
            cpa16(sb + o,             Ahi + asrc);
            cpa16(sb + GARR + o,      Alo + asrc);
            cpa16(sb + 2 * GARR + o,  Bhi + bsrc);
            cpa16(sb + 3 * GARR + o,  Blo + bsrc);
        }
    };
    auto load_stage_1p = [&](uint32_t sb, int kc) {
#pragma unroll
        for (int vv = 0; vv < 2; vv++) {
            int v = lv0 + vv;
            size_t asrc = (size_t)(m0 + lr) * KDIM + kc + v * 8;
            size_t bsrc = (size_t)(n0 + lr) * KDIM + kc + v * 8;
            uint32_t o = soff[vv];
            cpa16(sb + o,             Ahi + asrc);
            cpa16(sb + GARR + o,      Ahi + asrc + 32);
            cpa16(sb + 2 * GARR + o,  Bhi + bsrc);
            cpa16(sb + 3 * GARR + o,  Bhi + bsrc + 32);
        }
    };

    int lrow = lane & 15, lcol = lane >> 4;
    uint32_t x = (uint32_t)((lrow >> 1) & 3);
    uint32_t coff0 = (((uint32_t)lcol ^ x) << 4);
    uint32_t coff1 = ((((uint32_t)lcol + 2u) ^ x) << 4);
    uint32_t aoff[4], boff[2];
#pragma unroll
    for (int mf = 0; mf < 4; mf++)
        aoff[mf] = (uint32_t)((warp_m * 64 + mf * 16 + lrow) * 64);
#pragma unroll
    for (int pf = 0; pf < 2; pf++)
        boff[pf] = (uint32_t)((warp_n * 32 + pf * 16 + lrow) * 64);

    if (p3) {
        load_stage_p3(sbase, 0);
        CPA_COMMIT();
        load_stage_p3(sbase + GSTAGE, BK);
        CPA_COMMIT();

        uint32_t sb_c = sbase;
        uint32_t sb_l = sbase + 2u * GSTAGE;

        const int NITER = KDIM / BK;      // 32
        for (int c = 0; c < NITER; c++) {
            if (c < NITER - 1) { CPA_WAIT(1); } else { CPA_WAIT(0); }
            __syncthreads();
            if (c + 2 < NITER) {
                load_stage_p3(sb_l, (c + 2) * BK);
                CPA_COMMIT();
                sb_l += GSTAGE; if (sb_l == send) sb_l = sbase;
            }
            uint32_t sb = sb_c;
            sb_c += GSTAGE; if (sb_c == send) sb_c = sbase;

#pragma unroll
            for (int ki = 0; ki < 2; ki++) {
                uint32_t coff = ki ? coff1 : coff0;
                uint32_t ah[4][4];
#pragma unroll
                for (int mf = 0; mf < 4; mf++)
                    ldm_x4(ah[mf][0], ah[mf][1], ah[mf][2], ah[mf][3],
                           sb + aoff[mf] + coff);
                uint32_t bh[4][2];
#pragma unroll
                for (int pf = 0; pf < 2; pf++) {
                    uint32_t r0, r1, r2, r3;
                    ldm_x4(r0, r1, r2, r3, sb + 2 * GARR + boff[pf] + coff);
                    bh[pf * 2 + 0][0] = r0; bh[pf * 2 + 0][1] = r2;
                    bh[pf * 2 + 1][0] = r1; bh[pf * 2 + 1][1] = r3;
                }
#pragma unroll
                for (int mf = 0; mf < 4; mf++)
#pragma unroll
                    for (int nf = 0; nf < 4; nf++)
                        mma_f16(acc[mf][nf], ah[mf], bh[nf][0], bh[nf][1]);
                uint32_t al[4][4];
#pragma unroll
                for (int mf = 0; mf < 4; mf++)
                    ldm_x4(al[mf][0], al[mf][1], al[mf][2], al[mf][3],
                           sb + GARR + aoff[mf] + coff);
#pragma unroll
                for (int mf = 0; mf < 4; mf++)
#pragma unroll
                    for (int nf = 0; nf < 4; nf++)
                        mma_f16(acc[mf][nf], al[mf], bh[nf][0], bh[nf][1]);
                uint32_t bl[4][2];
#pragma unroll
                for (int pf = 0; pf < 2; pf++) {
                    uint32_t r0, r1, r2, r3;
                    ldm_x4(r0, r1, r2, r3, sb + 3 * GARR + boff[pf] + coff);
                    bl[pf * 2 + 0][0] = r0; bl[pf * 2 + 0][1] = r2;
                    bl[pf * 2 + 1][0] = r1; bl[pf * 2 + 1][1] = r3;
                }
#pragma unroll
                for (int mf = 0; mf < 4; mf++)
#pragma unroll
                    for (int nf = 0; nf < 4; nf++)
                        mma_f16(acc[mf][nf], ah[mf], bl[nf][0], bl[nf][1]);
            }
        }
    } else {
        load_stage_1p(sbase, 0);
        CPA_COMMIT();
        load_stage_1p(sbase + GSTAGE, 64);
        CPA_COMMIT();

        uint32_t sb_c = sbase;
        uint32_t sb_l = sbase + 2u * GSTAGE;

        const int NITER = KDIM / 64;      // 16
        for (int c = 0; c < NITER; c++) {
            if (c < NITER - 1) { CPA_WAIT(1); } else { CPA_WAIT(0); }
            __syncthreads();
            if (c + 2 < NITER) {
                load_stage_1p(sb_l, (c + 2) * 64);
                CPA_COMMIT();
                sb_l += GSTAGE; if (sb_l == send) sb_l = sbase;
            }
            uint32_t sb = sb_c;
            sb_c += GSTAGE; if (sb_c == send) sb_c = sbase;

#pragma unroll
            for (int sub = 0; sub < 2; sub++) {
                uint32_t asb = sb + (uint32_t)sub * GARR;
                uint32_t bsb = sb + (uint32_t)(2 + sub) * GARR;
#pragma unroll
                for (int ki = 0; ki < 2; ki++) {
                    uint32_t coff = ki ? coff1 : coff0;
                    uint32_t ah[4][4];
#pragma unroll
                    for (int mf = 0; mf < 4; mf++)
                        ldm_x4(ah[mf][0], ah[mf][1], ah[mf][2], ah[mf][3],
                               asb + aoff[mf] + coff);
                    uint32_t bh[4][2];
#pragma unroll
                    for (int pf = 0; pf < 2; pf++) {
                        uint32_t r0, r1, r2, r3;
                        ldm_x4(r0, r1, r2, r3, bsb + boff[pf] + coff);
                        bh[pf * 2 + 0][0] = r0; bh[pf * 2 + 0][1] = r2;
                        bh[pf * 2 + 1][0] = r1; bh[pf * 2 + 1][1] = r3;
                    }
#pragma unroll
                    for (int mf = 0; mf < 4; mf++)
#pragma unroll
                        for (int nf = 0; nf < 4; nf++)
                            mma_f16(acc[mf][nf], ah[mf], bh[nf][0], bh[nf][1]);
                }
            }
        }
    }

    // Epilogue
    int gID = lane >> 2, tcol = lane & 3;
#pragma unroll
    for (int mf = 0; mf < 4; mf++) {
#pragma unroll
        for (int nf = 0; nf < 4; nf++) {
            int c = n0 + warp_n * 32 + nf * 8 + tcol * 2;
            float2 bv = *(const float2*)&bias[c];
#pragma unroll
            for (int half = 0; half < 2; half++) {
                int r = m0 + warp_m * 64 + mf * 16 + gID + half * 8;
                float2 v;
                v.x = acc[mf][nf][half * 2 + 0] + bv.x;
                v.y = acc[mf][nf][half * 2 + 1] + bv.y;
                if (mode == 0) {
                    *(float2*)&outp[(size_t)r * EE + c] = v;
                } else {
                    int part = c >> 10, e = c & 1023, h = e >> 6, d0 = e & 63;
                    int b = r >> 11, s = r & 2047;
                    size_t base = (((size_t)(b * HH + h)) * SS + s) * DD + d0;
                    uint32_t hp = packf16(v.y, v.x);
                    if (part == 2) {
                        *(uint32_t*)&g_vhi[base] = hp;
                    } else {
                        uint32_t lp = packf16(v.y - hif16(hp), v.x - lof16(hp));
                        if (part == 0) {
                            *(uint32_t*)&g_qhi[base] = hp;
                            *(uint32_t*)&g_qlo[base] = lp;
                        } else {
                            *(uint32_t*)&g_khi[base] = hp;
                            *(uint32_t*)&g_klo[base] = lp;
                        }
                    }
                }
            }
        }
    }
}

// ---------------------------------------------------------------------------
// Tensor-core causal flash attention (R14 config): QK^T 3-pass fp16 split,
// PV 1-pass, Q frags in registers, 2-stage cp.async K/V, f16x2 MUFU softmax.
// ---------------------------------------------------------------------------
#define ALD 72
#define AQ_ELEMS (128 * ALD)
#define AKV_ARR (64 * ALD)
#define AKV_STAGE (3 * AKV_ARR)               // Khi,Klo,Vhi
#define OFF_KV0 (2 * AQ_ELEMS)
#define ATTN_SMEM_ELEMS (2 * AQ_ELEMS + 2 * AKV_STAGE)
#define ATTN_SMEM_BYTES (ATTN_SMEM_ELEMS * 2)   // 92160 B

#define LOG2E 1.4426950408889634f

__global__ __launch_bounds__(256, 2) void attn_mma_kernel()
{
    extern __shared__ __half dsm[];
    __half* Qhi_s = dsm;
    __half* Qlo_s = dsm + AQ_ELEMS;
    uint32_t kvbase = smem_u32(dsm + OFF_KV0);

    int qt = gridDim.x - 1 - blockIdx.x;        // big tiles first
    int h  = blockIdx.y;
    int b  = blockIdx.z;
    int tid = threadIdx.x, wid = tid >> 5, lane = tid & 31;

    size_t bh = ((size_t)(b * HH + h)) * SS * DD;
    const __half* Qhg = g_qhi + bh;
    const __half* Qlg = g_qlo + bh;
    const __half* Khg = g_khi + bh;
    const __half* Klg = g_klo + bh;
    const __half* Vhg = g_vhi + bh;

    int q0 = qt * 128;

    // Q tile into smem
#pragma unroll
    for (int t = 0; t < 4; t++) {
        int i = tid + t * 256;
        int r = i >> 3, v = i & 7;
        size_t src = (size_t)(q0 + r) * DD + v * 8;
        uint32_t so = (uint32_t)(r * ALD + v * 8);
        *(uint4*)&Qhi_s[so] = *(const uint4*)(Qhg + src);
        *(uint4*)&Qlo_s[so] = *(const uint4*)(Qlg + src);
    }

    auto load_kv = [&](int st, int k0) {
        uint32_t sb = kvbase + (uint32_t)(st * AKV_STAGE * 2);
#pragma unroll
        for (int t = 0; t < 2; t++) {
            int i = tid + t * 256;
            int r = i >> 3, v = i & 7;
            size_t src = (size_t)(k0 + r) * DD + v * 8;
            uint32_t o = (uint32_t)((r * ALD + v * 8) * 2);
            cpa16(sb + o,                   Khg + src);
            cpa16(sb + AKV_ARR * 2 + o,     Klg + src);
            cpa16(sb + 2 * AKV_ARR * 2 + o, Vhg + src);
        }
    };

    load_kv(0, 0);
    CPA_COMMIT();

    int lrow = lane & 15, lcol = lane >> 4;
    uint32_t qb_hi = smem_u32(Qhi_s) +
        (uint32_t)(((wid * 16 + lrow) * ALD + lcol * 8) * 2);
    uint32_t qb_lo = qb_hi + (uint32_t)(AQ_ELEMS * 2);
    uint32_t kvo = (uint32_t)((lrow * ALD + lcol * 8) * 2);

    // Hoist Q fragments into registers (one-time)
    __syncthreads();
    uint32_t qh[4][4], ql[4][4];
#pragma unroll
    for (int ks = 0; ks < 4; ks++) {
        ldm_x4(qh[ks][0], qh[ks][1], qh[ks][2], qh[ks][3],
               qb_hi + (uint32_t)(ks * 32));
        ldm_x4(ql[ks][0], ql[ks][1], ql[ks][2], ql[ks][3],
               qb_lo + (uint32_t)(ks * 32));
    }

    float o[8][4];
#pragma unroll
    for (int j = 0; j < 8; j++)
#pragma unroll
        for (int e = 0; e < 4; e++) o[j][e] = 0.0f;
    float m_[2] = {-1e30f, -1e30f}, l_[2] = {0.0f, 0.0f};

    int row0 = q0 + wid * 16 + (lane >> 2);
    const float scale2 = (1.0f / 16.0f) * LOG2E;
    const float maskv = -10000.0f * LOG2E;

    int ktmax = 2 * qt + 1;

    for (int kt = 0; kt <= ktmax; kt++) {
        CPA_WAIT(0);
        __syncthreads();
        if (kt + 1 <= ktmax) {
            load_kv((kt + 1) & 1, (kt + 1) * 64);
            CPA_COMMIT();
        }

        uint32_t sb = kvbase + (uint32_t)((kt & 1) * AKV_STAGE * 2);
        uint32_t kb_hi = sb + kvo;
        uint32_t kb_lo = sb + AKV_ARR * 2 + kvo;
        uint32_t vb_hi = sb + 2 * AKV_ARR * 2 + kvo;
        int k0 = kt * 64;

        float s[8][4];
#pragma unroll
        for (int nf = 0; nf < 8; nf++)
#pragma unroll
            for (int e = 0; e < 4; e++) s[nf][e] = 0.0f;

#pragma unroll
        for (int ks = 0; ks < 4; ks++) {
#pragma unroll
            for (int g = 0; g < 4; g++) {
                uint32_t off = (uint32_t)((g * 16 * ALD + ks * 16) * 2);
                uint32_t r0, r1, r2, r3, t0, t1, t2, t3;
                ldm_x4(r0, r1, r2, r3, kb_hi + off);
                ldm_x4(t0, t1, t2, t3, kb_lo + off);
                mma_f16(s[2 * g],     qh[ks], r0, r2);
                mma_f16(s[2 * g + 1], qh[ks], r1, r3);
                mma_f16(s[2 * g],     ql[ks], r0, r2);
                mma_f16(s[2 * g + 1], ql[ks], r1, r3);
                mma_f16(s[2 * g],     qh[ks], t0, t2);
                mma_f16(s[2 * g + 1], qh[ks], t1, t3);
            }
        }

        if (kt >= ktmax - 1) {
#pragma unroll
            for (int nf = 0; nf < 8; nf++) {
                int cb = k0 + nf * 8 + (lane & 3) * 2;
#pragma unroll
                for (int e = 0; e < 4; e++) {
                    int col = cb + (e & 1);
                    int row = (e < 2) ? row0 : row0 + 8;
                    float v = s[nf][e] * scale2;
                    s[nf][e] = (col > row) ? maskv : v;
                }
            }
        } else {
#pragma unroll
            for (int nf = 0; nf < 8; nf++)
#pragma unroll
                for (int e = 0; e < 4; e++) s[nf][e] *= scale2;
        }

        // online softmax (log2 domain): paired f16x2 exp; p = PV A-fragments
        uint32_t ps[2][8];
#pragma unroll
        for (int i = 0; i < 2; i++) {
            float mx = -1e30f;
#pragma unroll
            for (int nf = 0; nf < 8; nf++)
                mx = fmaxf(mx, fmaxf(s[nf][2 * i], s[nf][2 * i + 1]));
            mx = fmaxf(mx, __shfl_xor_sync(0xffffffffu, mx, 1));
            mx = fmaxf(mx, __shfl_xor_sync(0xffffffffu, mx, 2));
            float mn = fmaxf(m_[i], mx);
            float alpha = ex2(m_[i] - mn);
#pragma unroll
            for (int nf = 0; nf < 8; nf++)
                ps[i][nf] = ex2h2(packf16(s[nf][2 * i + 1] - mn,
                                          s[nf][2 * i] - mn));
            float sum = 0.0f;
#pragma unroll
            for (int nf = 0; nf < 8; nf++)
                sum += lof16(ps[i][nf]) + hif16(ps[i][nf]);
            sum += __shfl_xor_sync(0xffffffffu, sum, 1);
            sum += __shfl_xor_sync(0xffffffffu, sum, 2);
            l_[i] = l_[i] * alpha + sum;
            m_[i] = mn;
#pragma unroll
            for (int j = 0; j < 8; j++) {
                o[j][2 * i] *= alpha; o[j][2 * i + 1] *= alpha;
            }
        }

        // O += P V  (1-pass; P fragments = ps pairs)
#pragma unroll
        for (int c = 0; c < 4; c++) {
            uint32_t aph[4];
            aph[0] = ps[0][2 * c];
            aph[1] = ps[1][2 * c];
            aph[2] = ps[0][2 * c + 1];
            aph[3] = ps[1][2 * c + 1];
#pragma unroll
            for (int g = 0; g < 4; g++) {
                uint32_t off = (uint32_t)((c * 16 * ALD + g * 16) * 2);
                uint32_t r0, r1, r2, r3;
                ldm_x4_t(r0, r1, r2, r3, vb_hi + off);
                mma_f16(o[2 * g],     aph, r0, r1);
                mma_f16(o[2 * g + 1], aph, r2, r3);
            }
        }
    }

    // epilogue: O/l -> fp16 (hi only) merged-head [B*S, E]
    float inv0 = 1.0f / l_[0], inv1 = 1.0f / l_[1];
    int d0 = (lane & 3) * 2;
    size_t rb0 = ((size_t)(b * SS + row0)) * EE + h * DD;
    size_t rb1 = rb0 + (size_t)8 * EE;
#pragma unroll
    for (int j = 0; j < 8; j++) {
        int d = j * 8 + d0;
        float v0 = o[j][0] * inv0, v1 = o[j][1] * inv0;
        float v2 = o[j][2] * inv1, v3 = o[j][3] * inv1;
        *(uint32_t*)&g_ahi[rb0 + d] = packf16(v1, v0);
        *(uint32_t*)&g_ahi[rb1 + d] = packf16(v3, v2);
    }
}

// ---------------------------------------------------------------------------
extern "C" void kernel_launch(void* const* d_in, const int* in_sizes, int n_in,
                              void* d_out, int out_size)
{
    const float* hidden = (const float*)d_in[0];   // [B,S,E]
    const float* w_attn = (const float*)d_in[1];   // [E, 3E]
    const float* b_attn = (const float*)d_in[2];   // [3E]
    const float* w_proj = (const float*)d_in[3];   // [E, E]
    const float* b_proj = (const float*)d_in[4];   // [E]
    float* out = (float*)d_out;                    // [B,S,E] fp32

    prep_kernel<<<PREP_TOTAL_BLKS, 256>>>(hidden, w_attn, w_proj);

    cudaFuncSetAttribute(mma_gemm, cudaFuncAttributeMaxDynamicSharedMemorySize,
                         GEMM_SMEM_BYTES);
    mma_gemm<<<768, 256, GEMM_SMEM_BYTES>>>(b_attn, nullptr, 1);

    cudaFuncSetAttribute(attn_mma_kernel,
                         cudaFuncAttributeMaxDynamicSharedMemorySize,
                         ATTN_SMEM_BYTES);
    attn_mma_kernel<<<dim3(SS / 128, HH, BB), 256, ATTN_SMEM_BYTES>>>();

    mma_gemm<<<256, 256, GEMM_SMEM_BYTES>>>(b_proj, out, 0);
}